// round 11
// baseline (speedup 1.0000x reference)
#include <cuda_runtime.h>
#include <cstdint>
#include <math.h>

#define NTR 4096
#define NTE 8192
#define LDA 4096
#define LDB 8320          // 8192 test cols + y col + zero pad -> 65 * 128
#define NBLK 32           // 4096 / 128
#define BK 16
#define SLDA 132          // padded smem leading dim for 128-wide tiles

// ---------------- scratch (static device allocations; no cudaMalloc) -------
__device__ float g_K[(size_t)NTR * LDA];   // 64 MB  : K then L
__device__ float g_B[(size_t)NTR * LDB];   // 136 MB : [w*K_s | y | 0] then V
__device__ float g_par[4];                 // var, -0.5/ls^2, noise+1e-6

// ---------------- packed fp32 (Blackwell f32x2) helpers ------------------
__device__ __forceinline__ unsigned long long pack2(float x, float y) {
    unsigned long long r;
    asm("mov.b64 %0, {%1, %2};" : "=l"(r) : "f"(x), "f"(y));
    return r;
}
__device__ __forceinline__ void unpack2(unsigned long long v, float& x, float& y) {
    asm("mov.b64 {%0, %1}, %2;" : "=f"(x), "=f"(y) : "l"(v));
}
#define FFMA2(d, a, b) \
    asm("fma.rn.f32x2 %0, %1, %2, %0;" : "+l"(d) : "l"(a), "l"(b))

// ---------------- params -------------------------------------------------
__global__ void params_k(const float* rls, const float* rvar, const float* rnz) {
    float ls  = log1pf(expf(rls[0]));
    float var = log1pf(expf(rvar[0]));
    float nz  = log1pf(expf(rnz[0]));
    g_par[0] = var;
    g_par[1] = -0.5f / (ls * ls);
    g_par[2] = nz + 1e-6f;
}

// ---------------- build weighted K ---------------------------------------
__global__ void buildK_k(const float* __restrict__ xt, const float* __restrict__ w) {
    __shared__ float xi[16][8], xj[16][8], wi[16], wj[16];
    int bi = blockIdx.y * 16, bj = blockIdx.x * 16;
    int t = threadIdx.y * 16 + threadIdx.x;
    if (t < 128) {
        int r = t >> 3, c = t & 7;
        xi[r][c] = xt[(bi + r) * 8 + c];
        xj[r][c] = xt[(bj + r) * 8 + c];
    } else if (t < 144) wi[t - 128] = w[bi + t - 128];
    else if (t < 160)   wj[t - 144] = w[bj + t - 144];
    __syncthreads();
    int i = bi + threadIdx.y, j = bj + threadIdx.x;
    float d2 = 0.f;
#pragma unroll
    for (int c = 0; c < 8; c++) {
        float df = xi[threadIdx.y][c] - xj[threadIdx.x][c];
        d2 += df * df;
    }
    float v = g_par[0] * expf(g_par[1] * d2);
    float o = (i == j) ? (v + g_par[2]) : v * wi[threadIdx.y] * wj[threadIdx.x];
    g_K[(size_t)i * LDA + j] = o;
}

// ---------------- build B = [diag(w) K_s | y | 0] ------------------------
__global__ void buildB_k(const float* __restrict__ xt, const float* __restrict__ xe,
                         const float* __restrict__ w, const float* __restrict__ y) {
    __shared__ float xi[16][8], xj[16][8];
    int bi = blockIdx.y * 16, bj = blockIdx.x * 16;
    int t = threadIdx.y * 16 + threadIdx.x;
    if (t < 128) {
        int r = t >> 3, c = t & 7;
        xi[r][c] = xt[(bi + r) * 8 + c];
        int jr = bj + r;
        xj[r][c] = (jr < NTE) ? xe[jr * 8 + c] : 0.f;
    }
    __syncthreads();
    int i = bi + threadIdx.y, j = bj + threadIdx.x;
    float outv;
    if (j < NTE) {
        float d2 = 0.f;
#pragma unroll
        for (int c = 0; c < 8; c++) {
            float df = xi[threadIdx.y][c] - xj[threadIdx.x][c];
            d2 += df * df;
        }
        outv = w[i] * g_par[0] * expf(g_par[1] * d2);
    } else if (j == NTE) {
        outv = y[i];
    } else {
        outv = 0.f;
    }
    g_B[(size_t)i * LDB + j] = outv;
}

// ---------------- in-smem Cholesky, rank-4 steps (validated R10) ---------
__global__ __launch_bounds__(512) void potrf_k(int kb) {
    extern __shared__ float s[];   // [128][129]
    float* base = g_K + (size_t)(kb * 128) * LDA + kb * 128;
    int tid = threadIdx.x;
    int warp = tid >> 5, lane = tid & 31;   // 16 warps
    for (int idx = tid; idx < 128 * 128; idx += 512) {
        int r = idx >> 7, c = idx & 127;
        s[r * 129 + c] = base[(size_t)r * LDA + c];
    }
    __syncthreads();
    for (int j0 = 0; j0 < 128; j0 += 4) {
        float c00 = s[(j0+0)*129 + j0],   c10 = s[(j0+1)*129 + j0];
        float c11 = s[(j0+1)*129 + j0+1], c20 = s[(j0+2)*129 + j0];
        float c21 = s[(j0+2)*129 + j0+1], c22 = s[(j0+2)*129 + j0+2];
        float c30 = s[(j0+3)*129 + j0],   c31 = s[(j0+3)*129 + j0+1];
        float c32 = s[(j0+3)*129 + j0+2], c33 = s[(j0+3)*129 + j0+3];
        float l00 = sqrtf(c00);
        float i00 = 1.0f / l00;
        float l10 = c10 * i00, l20 = c20 * i00, l30 = c30 * i00;
        float l11 = sqrtf(c11 - l10 * l10);
        float i11 = 1.0f / l11;
        float l21 = (c21 - l20 * l10) * i11;
        float l31 = (c31 - l30 * l10) * i11;
        float l22 = sqrtf(c22 - l20 * l20 - l21 * l21);
        float i22 = 1.0f / l22;
        float l32 = (c32 - l30 * l20 - l31 * l21) * i22;
        float l33 = sqrtf(c33 - l30 * l30 - l31 * l31 - l32 * l32);
        float i33 = 1.0f / l33;
        if (tid < 128 && tid > j0 + 3) {
            float* R = s + tid * 129 + j0;
            float a0 = R[0], a1 = R[1], a2 = R[2], a3 = R[3];
            float b0 = a0 * i00;
            float b1 = (a1 - b0 * l10) * i11;
            float b2 = (a2 - b0 * l20 - b1 * l21) * i22;
            float b3 = (a3 - b0 * l30 - b1 * l31 - b2 * l32) * i33;
            R[0] = b0; R[1] = b1; R[2] = b2; R[3] = b3;
        }
        __syncthreads();
        if (tid >= j0 && tid <= j0 + 3 && tid < 128) {
            float* R = s + tid * 129 + j0;
            int r = tid - j0;
            if (r == 0)      { R[0] = l00; }
            else if (r == 1) { R[0] = l10; R[1] = l11; }
            else if (r == 2) { R[0] = l20; R[1] = l21; R[2] = l22; }
            else             { R[0] = l30; R[1] = l31; R[2] = l32; R[3] = l33; }
        }
        for (int i = j0 + 4 + warp; i < 128; i += 16) {
            float* Ri = s + i * 129;
            float li0 = Ri[j0], li1 = Ri[j0+1], li2 = Ri[j0+2], li3 = Ri[j0+3];
            for (int c = j0 + 4 + lane; c <= i; c += 32) {
                const float* Rc = s + c * 129 + j0;
                Ri[c] -= li0 * Rc[0] + li1 * Rc[1] + li2 * Rc[2] + li3 * Rc[3];
            }
        }
        __syncthreads();
    }
    for (int idx = tid; idx < 128 * 128; idx += 512) {
        int r = idx >> 7, c = idx & 127;
        base[(size_t)r * LDA + c] = s[r * 129 + c];
    }
}

// ---------------- panel TRSM: A21 <- A21 * L11^{-T}, thread-per-row ------
__global__ void panel_trsm_k(int kb) {
    extern __shared__ float sm[];
    float* Ls   = sm;                      // 128*129
    float* T    = sm + 128 * 129;          // 128*129
    float* rinv = T + 128 * 129;           // 128
    const float* Lbase = g_K + (size_t)(kb * 128) * LDA + kb * 128;
    float* Abase = g_K + (size_t)((kb + 1 + blockIdx.x) * 128) * LDA + kb * 128;
    int tid = threadIdx.x;
    for (int idx = tid; idx < 128 * 128; idx += 128) {
        int r = idx >> 7, c = idx & 127;
        Ls[r * 129 + c] = Lbase[(size_t)r * LDA + c];
        T[r * 129 + c]  = Abase[(size_t)r * LDA + c];
    }
    __syncthreads();
    rinv[tid] = 1.0f / Ls[tid * 129 + tid];
    __syncthreads();
    float* Tr = T + tid * 129;
    for (int j = 0; j < 128; j++) {
        float t = Tr[j];
        const float* Lj = Ls + j * 129;
        float s0 = 0.f, s1 = 0.f, s2 = 0.f, s3 = 0.f;
        int k = 0;
        for (; k + 4 <= j; k += 4) {
            s0 += Tr[k] * Lj[k];
            s1 += Tr[k + 1] * Lj[k + 1];
            s2 += Tr[k + 2] * Lj[k + 2];
            s3 += Tr[k + 3] * Lj[k + 3];
        }
        for (; k < j; k++) s0 += Tr[k] * Lj[k];
        t -= (s0 + s1) + (s2 + s3);
        Tr[j] = t * rinv[j];
    }
    __syncthreads();
    for (int idx = tid; idx < 128 * 128; idx += 128) {
        int r = idx >> 7, c = idx & 127;
        Abase[(size_t)r * LDA + c] = T[r * 129 + c];
    }
}

// ---------------- block-column forward solve of B, thread-per-column -----
__global__ void col_trsm_k(int kb) {
    extern __shared__ float sm[];
    float* Ls   = sm;                      // 128*129
    float* T    = sm + 128 * 129;          // 128*128
    float* rinv = T + 128 * 128;           // 128
    const float* Lbase = g_K + (size_t)(kb * 128) * LDA + kb * 128;
    float* Bbase = g_B + (size_t)(kb * 128) * LDB + blockIdx.x * 128;
    int tid = threadIdx.x;
    for (int idx = tid; idx < 128 * 128; idx += 128) {
        int r = idx >> 7, c = idx & 127;
        Ls[r * 129 + c] = Lbase[(size_t)r * LDA + c];
        T[idx] = Bbase[(size_t)r * LDB + c];
    }
    __syncthreads();
    rinv[tid] = 1.0f / Ls[tid * 129 + tid];
    __syncthreads();
    int c = tid;
    for (int i = 0; i < 128; i++) {
        float t = T[i * 128 + c];
        const float* Li = Ls + i * 129;
        float s0 = 0.f, s1 = 0.f, s2 = 0.f, s3 = 0.f;
        int k = 0;
        for (; k + 4 <= i; k += 4) {
            s0 += Li[k] * T[k * 128 + c];
            s1 += Li[k + 1] * T[(k + 1) * 128 + c];
            s2 += Li[k + 2] * T[(k + 2) * 128 + c];
            s3 += Li[k + 3] * T[(k + 3) * 128 + c];
        }
        for (; k < i; k++) s0 += Li[k] * T[k * 128 + c];
        t -= (s0 + s1) + (s2 + s3);
        T[i * 128 + c] = t * rinv[i];
    }
    __syncthreads();
    for (int idx = tid; idx < 128 * 128; idx += 128) {
        int r = idx >> 7, cc = idx & 127;
        Bbase[(size_t)r * LDB + cc] = T[idx];
    }
}

// ---------------- shared GEMM pieces (f32x2 FFMA2 core) ------------------
__device__ __forceinline__ void load_tile_rowsKcontig(float* dst, const float* src,
                                                      int ld, int tid) {
#pragma unroll
    for (int i = 0; i < 2; i++) {
        int s = tid + i * 256;
        int m = s >> 2, kq = (s & 3) * 4;
        float4 v = *(const float4*)(src + (size_t)m * ld + kq);
        dst[(kq + 0) * SLDA + m] = v.x;
        dst[(kq + 1) * SLDA + m] = v.y;
        dst[(kq + 2) * SLDA + m] = v.z;
        dst[(kq + 3) * SLDA + m] = v.w;
    }
}
__device__ __forceinline__ void load_tile_Ncontig(float* dst, const float* src,
                                                  int ld, int tid) {
#pragma unroll
    for (int i = 0; i < 2; i++) {
        int s = tid + i * 256;
        int k = s >> 5, nq = (s & 31) * 4;
        float4 v = *(const float4*)(src + (size_t)k * ld + nq);
        *(float4*)(dst + k * SLDA + nq) = v;
    }
}
// acc2[i][jp] = packed pair (acc[i][2jp], acc[i][2jp+1]); identical FMA order
__device__ __forceinline__ void mm_compute2(const float* As, const float* Bs,
                                            unsigned long long acc2[8][4],
                                            int ty, int tx) {
#pragma unroll
    for (int kk = 0; kk < BK; kk++) {
        float4 a0 = *(const float4*)(As + kk * SLDA + ty * 8);
        float4 a1 = *(const float4*)(As + kk * SLDA + ty * 8 + 4);
        float4 b0 = *(const float4*)(Bs + kk * SLDA + tx * 8);
        float4 b1 = *(const float4*)(Bs + kk * SLDA + tx * 8 + 4);
        float ra[8] = {a0.x, a0.y, a0.z, a0.w, a1.x, a1.y, a1.z, a1.w};
        unsigned long long rb[4];
        rb[0] = pack2(b0.x, b0.y);
        rb[1] = pack2(b0.z, b0.w);
        rb[2] = pack2(b1.x, b1.y);
        rb[3] = pack2(b1.z, b1.w);
#pragma unroll
        for (int i = 0; i < 8; i++) {
            unsigned long long aa = pack2(ra[i], ra[i]);
#pragma unroll
            for (int j = 0; j < 4; j++)
                FFMA2(acc2[i][j], aa, rb[j]);
        }
    }
}
__device__ __forceinline__ void acc2_init(unsigned long long acc2[8][4]) {
#pragma unroll
    for (int i = 0; i < 8; i++)
#pragma unroll
        for (int j = 0; j < 4; j++) acc2[i][j] = 0ull;
}
// RMW-subtract epilogue shared by syrk_chol / trsm_update
__device__ __forceinline__ void epi_sub(float* C, int ldc,
                                        unsigned long long acc2[8][4],
                                        int ty, int tx) {
#pragma unroll
    for (int i = 0; i < 8; i++) {
        float a0, a1, a2, a3, a4, a5, a6, a7;
        unpack2(acc2[i][0], a0, a1);
        unpack2(acc2[i][1], a2, a3);
        unpack2(acc2[i][2], a4, a5);
        unpack2(acc2[i][3], a6, a7);
        float* p = C + (size_t)(ty * 8 + i) * ldc + tx * 8;
        float4 v0 = *(float4*)p;
        v0.x -= a0; v0.y -= a1; v0.z -= a2; v0.w -= a3;
        *(float4*)p = v0;
        float4 v1 = *(float4*)(p + 4);
        v1.x -= a4; v1.y -= a5; v1.z -= a6; v1.w -= a7;
        *(float4*)(p + 4) = v1;
    }
}

// ---------------- Cholesky trailing update: A22 -= P P^T (lower only) ----
__global__ __launch_bounds__(256) void syrk_chol_k(int kb) {
    if (blockIdx.y > blockIdx.x) return;
    __shared__ float As[BK * SLDA], Bs[BK * SLDA];
    int tid = threadIdx.x, tx = tid & 15, ty = tid >> 4;
    const float* P = g_K + (size_t)((kb + 1) * 128) * LDA + kb * 128;
    const float* Arow = P + (size_t)blockIdx.x * 128 * LDA;
    const float* Brow = P + (size_t)blockIdx.y * 128 * LDA;
    float* C = g_K + (size_t)((kb + 1 + blockIdx.x) * 128) * LDA
                   + (kb + 1 + blockIdx.y) * 128;
    unsigned long long acc2[8][4];
    acc2_init(acc2);
    for (int k0 = 0; k0 < 128; k0 += BK) {
        load_tile_rowsKcontig(As, Arow + k0, LDA, tid);
        load_tile_rowsKcontig(Bs, Brow + k0, LDA, tid);
        __syncthreads();
        mm_compute2(As, Bs, acc2, ty, tx);
        __syncthreads();
    }
    epi_sub(C, LDA, acc2, ty, tx);
}

// ---------------- TRSM trailing update: B_below -= L_panel * V_k ---------
__global__ __launch_bounds__(256) void trsm_update_k(int kb) {
    __shared__ float As[BK * SLDA], Bs[BK * SLDA];
    int tid = threadIdx.x, tx = tid & 15, ty = tid >> 4;
    const float* A = g_K + (size_t)((kb + 1 + blockIdx.x) * 128) * LDA + kb * 128;
    const float* V = g_B + (size_t)(kb * 128) * LDB + blockIdx.y * 128;
    float* C = g_B + (size_t)((kb + 1 + blockIdx.x) * 128) * LDB + blockIdx.y * 128;
    unsigned long long acc2[8][4];
    acc2_init(acc2);
    for (int k0 = 0; k0 < 128; k0 += BK) {
        load_tile_rowsKcontig(As, A + k0, LDA, tid);
        load_tile_Ncontig(Bs, V + (size_t)k0 * LDB, LDB, tid);
        __syncthreads();
        mm_compute2(As, Bs, acc2, ty, tx);
        __syncthreads();
    }
    epi_sub(C, LDB, acc2, ty, tx);
}

// ---------------- cov = K_ss - V^T V (triangle + mirror, fused K_ss) -----
__global__ __launch_bounds__(256) void cov_syrk_k(const float* __restrict__ xe,
                                                  float* __restrict__ out) {
    int bx = blockIdx.x, by = blockIdx.y;
    if (by > bx) return;
    __shared__ float As[BK * SLDA], Bs[BK * SLDA];
    __shared__ float xr[128 * 8], xc[128 * 8];
    int tid = threadIdx.x, tx = tid & 15, ty = tid >> 4;
    for (int idx = tid; idx < 1024; idx += 256) {
        xr[idx] = xe[(size_t)bx * 1024 + idx];
        xc[idx] = xe[(size_t)by * 1024 + idx];
    }
    const float* Aop = g_B + bx * 128;
    const float* Bop = g_B + by * 128;
    unsigned long long acc2[8][4];
    acc2_init(acc2);
    for (int k0 = 0; k0 < NTR; k0 += BK) {
        load_tile_Ncontig(As, Aop + (size_t)k0 * LDB, LDB, tid);
        load_tile_Ncontig(Bs, Bop + (size_t)k0 * LDB, LDB, tid);
        __syncthreads();
        mm_compute2(As, Bs, acc2, ty, tx);
        __syncthreads();
    }
    float var = g_par[0], ngc = g_par[1];
    float* cov = out + NTE;
#pragma unroll
    for (int i = 0; i < 8; i++) {
        float av[8];
        unpack2(acc2[i][0], av[0], av[1]);
        unpack2(acc2[i][1], av[2], av[3]);
        unpack2(acc2[i][2], av[4], av[5]);
        unpack2(acc2[i][3], av[6], av[7]);
        int jg = bx * 128 + ty * 8 + i;
#pragma unroll
        for (int jj = 0; jj < 8; jj++) {
            int kg = by * 128 + tx * 8 + jj;
            float d2 = 0.f;
#pragma unroll
            for (int c = 0; c < 8; c++) {
                float df = xr[(ty * 8 + i) * 8 + c] - xc[(tx * 8 + jj) * 8 + c];
                d2 += df * df;
            }
            float kss = var * expf(ngc * d2);
            if (jg == kg) kss += 1e-6f;
            float val = kss - av[jj];
            cov[(size_t)jg * NTE + kg] = val;
            cov[(size_t)kg * NTE + jg] = val;
        }
    }
}

// ---------------- mu = V^T z (z = last live column of B) -----------------
__global__ void mu_k_(float* __restrict__ out) {
    int j = blockIdx.x * 256 + threadIdx.x;
    const float* Bj = g_B + j;
    const float* Bz = g_B + NTE;
    float s0 = 0.f, s1 = 0.f, s2 = 0.f, s3 = 0.f;
    for (int i = 0; i < NTR; i += 4) {
        s0 += Bj[(size_t)(i + 0) * LDB] * Bz[(size_t)(i + 0) * LDB];
        s1 += Bj[(size_t)(i + 1) * LDB] * Bz[(size_t)(i + 1) * LDB];
        s2 += Bj[(size_t)(i + 2) * LDB] * Bz[(size_t)(i + 2) * LDB];
        s3 += Bj[(size_t)(i + 3) * LDB] * Bz[(size_t)(i + 3) * LDB];
    }
    out[j] = (s0 + s1) + (s2 + s3);
}

// ---------------- launch -------------------------------------------------
extern "C" void kernel_launch(void* const* d_in, const int* in_sizes, int n_in,
                              void* d_out, int out_size) {
    const float* xtr  = (const float*)d_in[0];
    const float* y    = (const float*)d_in[1];
    const float* w    = (const float*)d_in[2];
    const float* xte  = (const float*)d_in[3];
    const float* rls  = (const float*)d_in[4];
    const float* rvar = (const float*)d_in[5];
    const float* rnz  = (const float*)d_in[6];
    float* out = (float*)d_out;

    const int smem_potrf = 128 * 129 * 4;
    const int smem_panel = (2 * 128 * 129 + 128) * 4;
    const int smem_col   = (128 * 129 + 128 * 128 + 128) * 4;
    cudaFuncSetAttribute(potrf_k, cudaFuncAttributeMaxDynamicSharedMemorySize, smem_potrf);
    cudaFuncSetAttribute(panel_trsm_k, cudaFuncAttributeMaxDynamicSharedMemorySize, smem_panel);
    cudaFuncSetAttribute(col_trsm_k, cudaFuncAttributeMaxDynamicSharedMemorySize, smem_col);

    params_k<<<1, 1>>>(rls, rvar, rnz);
    buildK_k<<<dim3(256, 256), dim3(16, 16)>>>(xtr, w);
    buildB_k<<<dim3(520, 256), dim3(16, 16)>>>(xtr, xte, w, y);

    for (int kb = 0; kb < NBLK; kb++) {
        potrf_k<<<1, 512, smem_potrf>>>(kb);
        int mrem = NBLK - kb - 1;
        if (mrem > 0) {
            panel_trsm_k<<<mrem, 128, smem_panel>>>(kb);
            syrk_chol_k<<<dim3(mrem, mrem), 256>>>(kb);
        }
    }
    for (int kb = 0; kb < NBLK; kb++) {
        col_trsm_k<<<65, 128, smem_col>>>(kb);
        int mrem = NBLK - kb - 1;
        if (mrem > 0) trsm_update_k<<<dim3(mrem, 65), 256>>>(kb);
    }
    mu_k_<<<NTE / 256, 256>>>(out);
    cov_syrk_k<<<dim3(64, 64), 256>>>(xte, out);
}

// round 12
// speedup vs baseline: 1.1868x; 1.1868x over previous
#include <cuda_runtime.h>
#include <cstdint>
#include <math.h>

#define NTR 4096
#define NTE 8192
#define LDA 4096
#define LDB 8320          // 8192 test cols + y col + zero pad -> 65 * 128
#define NBLK 32           // 4096 / 128
#define BK 16
#define SLDA 132          // padded smem leading dim for 128-wide tiles

// ---------------- scratch (static device allocations; no cudaMalloc) -------
__device__ float g_K[(size_t)NTR * LDA];   // 64 MB  : K then L
__device__ float g_B[(size_t)NTR * LDB];   // 136 MB : [w*K_s | y | 0] then V
__device__ float g_par[4];                 // var, -0.5/ls^2, noise+1e-6

// ---------------- params -------------------------------------------------
__global__ void params_k(const float* rls, const float* rvar, const float* rnz) {
    float ls  = log1pf(expf(rls[0]));
    float var = log1pf(expf(rvar[0]));
    float nz  = log1pf(expf(rnz[0]));
    g_par[0] = var;
    g_par[1] = -0.5f / (ls * ls);
    g_par[2] = nz + 1e-6f;
}

// ---------------- build weighted K ---------------------------------------
__global__ void buildK_k(const float* __restrict__ xt, const float* __restrict__ w) {
    __shared__ float xi[16][8], xj[16][8], wi[16], wj[16];
    int bi = blockIdx.y * 16, bj = blockIdx.x * 16;
    int t = threadIdx.y * 16 + threadIdx.x;
    if (t < 128) {
        int r = t >> 3, c = t & 7;
        xi[r][c] = xt[(bi + r) * 8 + c];
        xj[r][c] = xt[(bj + r) * 8 + c];
    } else if (t < 144) wi[t - 128] = w[bi + t - 128];
    else if (t < 160)   wj[t - 144] = w[bj + t - 144];
    __syncthreads();
    int i = bi + threadIdx.y, j = bj + threadIdx.x;
    float d2 = 0.f;
#pragma unroll
    for (int c = 0; c < 8; c++) {
        float df = xi[threadIdx.y][c] - xj[threadIdx.x][c];
        d2 += df * df;
    }
    float v = g_par[0] * expf(g_par[1] * d2);
    float o = (i == j) ? (v + g_par[2]) : v * wi[threadIdx.y] * wj[threadIdx.x];
    g_K[(size_t)i * LDA + j] = o;
}

// ---------------- build B = [diag(w) K_s | y | 0] ------------------------
__global__ void buildB_k(const float* __restrict__ xt, const float* __restrict__ xe,
                         const float* __restrict__ w, const float* __restrict__ y) {
    __shared__ float xi[16][8], xj[16][8];
    int bi = blockIdx.y * 16, bj = blockIdx.x * 16;
    int t = threadIdx.y * 16 + threadIdx.x;
    if (t < 128) {
        int r = t >> 3, c = t & 7;
        xi[r][c] = xt[(bi + r) * 8 + c];
        int jr = bj + r;
        xj[r][c] = (jr < NTE) ? xe[jr * 8 + c] : 0.f;
    }
    __syncthreads();
    int i = bi + threadIdx.y, j = bj + threadIdx.x;
    float outv;
    if (j < NTE) {
        float d2 = 0.f;
#pragma unroll
        for (int c = 0; c < 8; c++) {
            float df = xi[threadIdx.y][c] - xj[threadIdx.x][c];
            d2 += df * df;
        }
        outv = w[i] * g_par[0] * expf(g_par[1] * d2);
    } else if (j == NTE) {
        outv = y[i];
    } else {
        outv = 0.f;
    }
    g_B[(size_t)i * LDB + j] = outv;
}

// ---------------- in-smem Cholesky, rank-4 steps (validated R10) ---------
__global__ __launch_bounds__(512) void potrf_k(int kb) {
    extern __shared__ float s[];   // [128][129]
    float* base = g_K + (size_t)(kb * 128) * LDA + kb * 128;
    int tid = threadIdx.x;
    int warp = tid >> 5, lane = tid & 31;   // 16 warps
    for (int idx = tid; idx < 128 * 128; idx += 512) {
        int r = idx >> 7, c = idx & 127;
        s[r * 129 + c] = base[(size_t)r * LDA + c];
    }
    __syncthreads();
    for (int j0 = 0; j0 < 128; j0 += 4) {
        float c00 = s[(j0+0)*129 + j0],   c10 = s[(j0+1)*129 + j0];
        float c11 = s[(j0+1)*129 + j0+1], c20 = s[(j0+2)*129 + j0];
        float c21 = s[(j0+2)*129 + j0+1], c22 = s[(j0+2)*129 + j0+2];
        float c30 = s[(j0+3)*129 + j0],   c31 = s[(j0+3)*129 + j0+1];
        float c32 = s[(j0+3)*129 + j0+2], c33 = s[(j0+3)*129 + j0+3];
        float l00 = sqrtf(c00);
        float i00 = 1.0f / l00;
        float l10 = c10 * i00, l20 = c20 * i00, l30 = c30 * i00;
        float l11 = sqrtf(c11 - l10 * l10);
        float i11 = 1.0f / l11;
        float l21 = (c21 - l20 * l10) * i11;
        float l31 = (c31 - l30 * l10) * i11;
        float l22 = sqrtf(c22 - l20 * l20 - l21 * l21);
        float i22 = 1.0f / l22;
        float l32 = (c32 - l30 * l20 - l31 * l21) * i22;
        float l33 = sqrtf(c33 - l30 * l30 - l31 * l31 - l32 * l32);
        float i33 = 1.0f / l33;
        if (tid < 128 && tid > j0 + 3) {
            float* R = s + tid * 129 + j0;
            float a0 = R[0], a1 = R[1], a2 = R[2], a3 = R[3];
            float b0 = a0 * i00;
            float b1 = (a1 - b0 * l10) * i11;
            float b2 = (a2 - b0 * l20 - b1 * l21) * i22;
            float b3 = (a3 - b0 * l30 - b1 * l31 - b2 * l32) * i33;
            R[0] = b0; R[1] = b1; R[2] = b2; R[3] = b3;
        }
        __syncthreads();
        if (tid >= j0 && tid <= j0 + 3 && tid < 128) {
            float* R = s + tid * 129 + j0;
            int r = tid - j0;
            if (r == 0)      { R[0] = l00; }
            else if (r == 1) { R[0] = l10; R[1] = l11; }
            else if (r == 2) { R[0] = l20; R[1] = l21; R[2] = l22; }
            else             { R[0] = l30; R[1] = l31; R[2] = l32; R[3] = l33; }
        }
        for (int i = j0 + 4 + warp; i < 128; i += 16) {
            float* Ri = s + i * 129;
            float li0 = Ri[j0], li1 = Ri[j0+1], li2 = Ri[j0+2], li3 = Ri[j0+3];
            for (int c = j0 + 4 + lane; c <= i; c += 32) {
                const float* Rc = s + c * 129 + j0;
                Ri[c] -= li0 * Rc[0] + li1 * Rc[1] + li2 * Rc[2] + li3 * Rc[3];
            }
        }
        __syncthreads();
    }
    for (int idx = tid; idx < 128 * 128; idx += 512) {
        int r = idx >> 7, c = idx & 127;
        base[(size_t)r * LDA + c] = s[r * 129 + c];
    }
}

// ---------------- panel TRSM: A21 <- A21 * L11^{-T}, thread-per-row ------
__global__ void panel_trsm_k(int kb) {
    extern __shared__ float sm[];
    float* Ls   = sm;                      // 128*129
    float* T    = sm + 128 * 129;          // 128*129
    float* rinv = T + 128 * 129;           // 128
    const float* Lbase = g_K + (size_t)(kb * 128) * LDA + kb * 128;
    float* Abase = g_K + (size_t)((kb + 1 + blockIdx.x) * 128) * LDA + kb * 128;
    int tid = threadIdx.x;
    for (int idx = tid; idx < 128 * 128; idx += 128) {
        int r = idx >> 7, c = idx & 127;
        Ls[r * 129 + c] = Lbase[(size_t)r * LDA + c];
        T[r * 129 + c]  = Abase[(size_t)r * LDA + c];
    }
    __syncthreads();
    rinv[tid] = 1.0f / Ls[tid * 129 + tid];
    __syncthreads();
    float* Tr = T + tid * 129;
    for (int j = 0; j < 128; j++) {
        float t = Tr[j];
        const float* Lj = Ls + j * 129;
        float s0 = 0.f, s1 = 0.f, s2 = 0.f, s3 = 0.f;
        int k = 0;
        for (; k + 4 <= j; k += 4) {
            s0 += Tr[k] * Lj[k];
            s1 += Tr[k + 1] * Lj[k + 1];
            s2 += Tr[k + 2] * Lj[k + 2];
            s3 += Tr[k + 3] * Lj[k + 3];
        }
        for (; k < j; k++) s0 += Tr[k] * Lj[k];
        t -= (s0 + s1) + (s2 + s3);
        Tr[j] = t * rinv[j];
    }
    __syncthreads();
    for (int idx = tid; idx < 128 * 128; idx += 128) {
        int r = idx >> 7, c = idx & 127;
        Abase[(size_t)r * LDA + c] = T[r * 129 + c];
    }
}

// ---------------- block-column forward solve of B, thread-per-column -----
__global__ void col_trsm_k(int kb) {
    extern __shared__ float sm[];
    float* Ls   = sm;                      // 128*129
    float* T    = sm + 128 * 129;          // 128*128
    float* rinv = T + 128 * 128;           // 128
    const float* Lbase = g_K + (size_t)(kb * 128) * LDA + kb * 128;
    float* Bbase = g_B + (size_t)(kb * 128) * LDB + blockIdx.x * 128;
    int tid = threadIdx.x;
    for (int idx = tid; idx < 128 * 128; idx += 128) {
        int r = idx >> 7, c = idx & 127;
        Ls[r * 129 + c] = Lbase[(size_t)r * LDA + c];
        T[idx] = Bbase[(size_t)r * LDB + c];
    }
    __syncthreads();
    rinv[tid] = 1.0f / Ls[tid * 129 + tid];
    __syncthreads();
    int c = tid;
    for (int i = 0; i < 128; i++) {
        float t = T[i * 128 + c];
        const float* Li = Ls + i * 129;
        float s0 = 0.f, s1 = 0.f, s2 = 0.f, s3 = 0.f;
        int k = 0;
        for (; k + 4 <= i; k += 4) {
            s0 += Li[k] * T[k * 128 + c];
            s1 += Li[k + 1] * T[(k + 1) * 128 + c];
            s2 += Li[k + 2] * T[(k + 2) * 128 + c];
            s3 += Li[k + 3] * T[(k + 3) * 128 + c];
        }
        for (; k < i; k++) s0 += Li[k] * T[k * 128 + c];
        t -= (s0 + s1) + (s2 + s3);
        T[i * 128 + c] = t * rinv[i];
    }
    __syncthreads();
    for (int idx = tid; idx < 128 * 128; idx += 128) {
        int r = idx >> 7, cc = idx & 127;
        Bbase[(size_t)r * LDB + cc] = T[idx];
    }
}

// ---------------- shared SIMT GEMM pieces (128x128x16, 256 thr, 8x8) -----
__device__ __forceinline__ void load_tile_rowsKcontig(float* dst, const float* src,
                                                      int ld, int tid) {
#pragma unroll
    for (int i = 0; i < 2; i++) {
        int s = tid + i * 256;
        int m = s >> 2, kq = (s & 3) * 4;
        float4 v = *(const float4*)(src + (size_t)m * ld + kq);
        dst[(kq + 0) * SLDA + m] = v.x;
        dst[(kq + 1) * SLDA + m] = v.y;
        dst[(kq + 2) * SLDA + m] = v.z;
        dst[(kq + 3) * SLDA + m] = v.w;
    }
}
__device__ __forceinline__ void load_tile_Ncontig(float* dst, const float* src,
                                                  int ld, int tid) {
#pragma unroll
    for (int i = 0; i < 2; i++) {
        int s = tid + i * 256;
        int k = s >> 5, nq = (s & 31) * 4;
        float4 v = *(const float4*)(src + (size_t)k * ld + nq);
        *(float4*)(dst + k * SLDA + nq) = v;
    }
}
__device__ __forceinline__ void mm_compute(const float* As, const float* Bs,
                                           float acc[8][8], int ty, int tx) {
#pragma unroll
    for (int kk = 0; kk < BK; kk++) {
        float4 a0 = *(const float4*)(As + kk * SLDA + ty * 8);
        float4 a1 = *(const float4*)(As + kk * SLDA + ty * 8 + 4);
        float4 b0 = *(const float4*)(Bs + kk * SLDA + tx * 8);
        float4 b1 = *(const float4*)(Bs + kk * SLDA + tx * 8 + 4);
        float ra[8] = {a0.x, a0.y, a0.z, a0.w, a1.x, a1.y, a1.z, a1.w};
        float rb[8] = {b0.x, b0.y, b0.z, b0.w, b1.x, b1.y, b1.z, b1.w};
#pragma unroll
        for (int i = 0; i < 8; i++)
#pragma unroll
            for (int j = 0; j < 8; j++)
                acc[i][j] += ra[i] * rb[j];
    }
}

// ---------------- Cholesky trailing update: A22 -= P P^T (lower only) ----
__global__ __launch_bounds__(256) void syrk_chol_k(int kb) {
    if (blockIdx.y > blockIdx.x) return;
    __shared__ float As[BK * SLDA], Bs[BK * SLDA];
    int tid = threadIdx.x, tx = tid & 15, ty = tid >> 4;
    const float* P = g_K + (size_t)((kb + 1) * 128) * LDA + kb * 128;
    const float* Arow = P + (size_t)blockIdx.x * 128 * LDA;
    const float* Brow = P + (size_t)blockIdx.y * 128 * LDA;
    float* C = g_K + (size_t)((kb + 1 + blockIdx.x) * 128) * LDA
                   + (kb + 1 + blockIdx.y) * 128;
    float acc[8][8];
#pragma unroll
    for (int i = 0; i < 8; i++)
#pragma unroll
        for (int j = 0; j < 8; j++) acc[i][j] = 0.f;
    for (int k0 = 0; k0 < 128; k0 += BK) {
        load_tile_rowsKcontig(As, Arow + k0, LDA, tid);
        load_tile_rowsKcontig(Bs, Brow + k0, LDA, tid);
        __syncthreads();
        mm_compute(As, Bs, acc, ty, tx);
        __syncthreads();
    }
#pragma unroll
    for (int i = 0; i < 8; i++) {
        float* p = C + (size_t)(ty * 8 + i) * LDA + tx * 8;
        float4 v0 = *(float4*)p;
        v0.x -= acc[i][0]; v0.y -= acc[i][1]; v0.z -= acc[i][2]; v0.w -= acc[i][3];
        *(float4*)p = v0;
        float4 v1 = *(float4*)(p + 4);
        v1.x -= acc[i][4]; v1.y -= acc[i][5]; v1.z -= acc[i][6]; v1.w -= acc[i][7];
        *(float4*)(p + 4) = v1;
    }
}

// ---------------- TRSM trailing update: B_below -= L_panel * V_k ---------
__global__ __launch_bounds__(256) void trsm_update_k(int kb) {
    __shared__ float As[BK * SLDA], Bs[BK * SLDA];
    int tid = threadIdx.x, tx = tid & 15, ty = tid >> 4;
    const float* A = g_K + (size_t)((kb + 1 + blockIdx.x) * 128) * LDA + kb * 128;
    const float* V = g_B + (size_t)(kb * 128) * LDB + blockIdx.y * 128;
    float* C = g_B + (size_t)((kb + 1 + blockIdx.x) * 128) * LDB + blockIdx.y * 128;
    float acc[8][8];
#pragma unroll
    for (int i = 0; i < 8; i++)
#pragma unroll
        for (int j = 0; j < 8; j++) acc[i][j] = 0.f;
    for (int k0 = 0; k0 < 128; k0 += BK) {
        load_tile_rowsKcontig(As, A + k0, LDA, tid);
        load_tile_Ncontig(Bs, V + (size_t)k0 * LDB, LDB, tid);
        __syncthreads();
        mm_compute(As, Bs, acc, ty, tx);
        __syncthreads();
    }
#pragma unroll
    for (int i = 0; i < 8; i++) {
        float* p = C + (size_t)(ty * 8 + i) * LDB + tx * 8;
        float4 v0 = *(float4*)p;
        v0.x -= acc[i][0]; v0.y -= acc[i][1]; v0.z -= acc[i][2]; v0.w -= acc[i][3];
        *(float4*)p = v0;
        float4 v1 = *(float4*)(p + 4);
        v1.x -= acc[i][4]; v1.y -= acc[i][5]; v1.z -= acc[i][6]; v1.w -= acc[i][7];
        *(float4*)(p + 4) = v1;
    }
}

// ---------------- cov = K_ss - V^T V (triangle + mirror, fused K_ss) -----
__global__ __launch_bounds__(256) void cov_syrk_k(const float* __restrict__ xe,
                                                  float* __restrict__ out) {
    int bx = blockIdx.x, by = blockIdx.y;
    if (by > bx) return;
    __shared__ float As[BK * SLDA], Bs[BK * SLDA];
    __shared__ float xr[128 * 8], xc[128 * 8];
    int tid = threadIdx.x, tx = tid & 15, ty = tid >> 4;
    for (int idx = tid; idx < 1024; idx += 256) {
        xr[idx] = xe[(size_t)bx * 1024 + idx];
        xc[idx] = xe[(size_t)by * 1024 + idx];
    }
    const float* Aop = g_B + bx * 128;
    const float* Bop = g_B + by * 128;
    float acc[8][8];
#pragma unroll
    for (int i = 0; i < 8; i++)
#pragma unroll
        for (int j = 0; j < 8; j++) acc[i][j] = 0.f;
    for (int k0 = 0; k0 < NTR; k0 += BK) {
        load_tile_Ncontig(As, Aop + (size_t)k0 * LDB, LDB, tid);
        load_tile_Ncontig(Bs, Bop + (size_t)k0 * LDB, LDB, tid);
        __syncthreads();
        mm_compute(As, Bs, acc, ty, tx);
        __syncthreads();
    }
    float var = g_par[0], ngc = g_par[1];
    float* cov = out + NTE;
#pragma unroll
    for (int i = 0; i < 8; i++) {
        int jg = bx * 128 + ty * 8 + i;
#pragma unroll
        for (int jj = 0; jj < 8; jj++) {
            int kg = by * 128 + tx * 8 + jj;
            float d2 = 0.f;
#pragma unroll
            for (int c = 0; c < 8; c++) {
                float df = xr[(ty * 8 + i) * 8 + c] - xc[(tx * 8 + jj) * 8 + c];
                d2 += df * df;
            }
            float kss = var * expf(ngc * d2);
            if (jg == kg) kss += 1e-6f;
            float val = kss - acc[i][jj];
            cov[(size_t)jg * NTE + kg] = val;
            cov[(size_t)kg * NTE + jg] = val;
        }
    }
}

// ---------------- mu = V^T z (z = last live column of B) -----------------
__global__ void mu_k_(float* __restrict__ out) {
    int j = blockIdx.x * 256 + threadIdx.x;
    const float* Bj = g_B + j;
    const float* Bz = g_B + NTE;
    float s0 = 0.f, s1 = 0.f, s2 = 0.f, s3 = 0.f;
    for (int i = 0; i < NTR; i += 4) {
        s0 += Bj[(size_t)(i + 0) * LDB] * Bz[(size_t)(i + 0) * LDB];
        s1 += Bj[(size_t)(i + 1) * LDB] * Bz[(size_t)(i + 1) * LDB];
        s2 += Bj[(size_t)(i + 2) * LDB] * Bz[(size_t)(i + 2) * LDB];
        s3 += Bj[(size_t)(i + 3) * LDB] * Bz[(size_t)(i + 3) * LDB];
    }
    out[j] = (s0 + s1) + (s2 + s3);
}

// ---------------- launch (two-stream forked graph) -----------------------
extern "C" void kernel_launch(void* const* d_in, const int* in_sizes, int n_in,
                              void* d_out, int out_size) {
    const float* xtr  = (const float*)d_in[0];
    const float* y    = (const float*)d_in[1];
    const float* w    = (const float*)d_in[2];
    const float* xte  = (const float*)d_in[3];
    const float* rls  = (const float*)d_in[4];
    const float* rvar = (const float*)d_in[5];
    const float* rnz  = (const float*)d_in[6];
    float* out = (float*)d_out;

    const int smem_potrf = 128 * 129 * 4;
    const int smem_panel = (2 * 128 * 129 + 128) * 4;
    const int smem_col   = (128 * 129 + 128 * 128 + 128) * 4;
    cudaFuncSetAttribute(potrf_k, cudaFuncAttributeMaxDynamicSharedMemorySize, smem_potrf);
    cudaFuncSetAttribute(panel_trsm_k, cudaFuncAttributeMaxDynamicSharedMemorySize, smem_panel);
    cudaFuncSetAttribute(col_trsm_k, cudaFuncAttributeMaxDynamicSharedMemorySize, smem_col);

    // Host-side stream/event objects (no device memory). Created per call,
    // intentionally not destroyed while capture may still be active.
    cudaStream_t s2;
    cudaStreamCreate(&s2);
    cudaEvent_t evPanel[NBLK], evDone;
    for (int i = 0; i < NBLK; i++)
        cudaEventCreateWithFlags(&evPanel[i], cudaEventDisableTiming);
    cudaEventCreateWithFlags(&evDone, cudaEventDisableTiming);

    params_k<<<1, 1>>>(rls, rvar, rnz);
    buildK_k<<<dim3(256, 256), dim3(16, 16)>>>(xtr, w);
    buildB_k<<<dim3(520, 256), dim3(16, 16)>>>(xtr, xte, w, y);

    for (int kb = 0; kb < NBLK; kb++) {
        int mrem = NBLK - kb - 1;
        potrf_k<<<1, 512, smem_potrf>>>(kb);
        if (mrem > 0)
            panel_trsm_k<<<mrem, 128, smem_panel>>>(kb);
        // fork: B-solve chain for column kb runs on s2, overlapping with the
        // Cholesky chain's syrk/potrf of later columns.
        cudaEventRecord(evPanel[kb], 0);
        cudaStreamWaitEvent(s2, evPanel[kb], 0);
        col_trsm_k<<<65, 128, smem_col, s2>>>(kb);
        if (mrem > 0) {
            trsm_update_k<<<dim3(mrem, 65), 256, 0, s2>>>(kb);
            syrk_chol_k<<<dim3(mrem, mrem), 256>>>(kb);
        }
    }
    // join: mu/cov need the fully solved V in g_B.
    cudaEventRecord(evDone, s2);
    cudaStreamWaitEvent(0, evDone, 0);

    mu_k_<<<NTE / 256, 256>>>(out);
    cov_syrk_k<<<dim3(64, 64), 256>>>(xte, out);
}